// round 10
// baseline (speedup 1.0000x reference)
#include <cuda_runtime.h>

#define S 64
#define MAXT 262144
#define L 512
#define NCMAX ((MAXT + L - 1) / L)

// ---- scratch (__device__ globals: no allocation allowed) ----
__device__ float g_e_buf[(size_t)(MAXT + 8) * S];              // e_t rows (+pad rows)
__device__ int g_rollpad[MAXT + 96];                           // rolls padded with last value
__device__ unsigned char g_walk[(size_t)NCMAX * S * L];        // per-chunk walks (16 MB)
__device__ int g_boundary[NCMAX + 2];
__device__ int g_final_state;
__device__ float g_final_score;

__device__ __forceinline__ float fmax3(float a, float b, float c) {
    return fmaxf(fmaxf(a, b), c);
}

// =====================================================================
// Kernel 0a: pad rolls so the serial loop needs no clamping
// =====================================================================
__global__ void prep_kernel(const int* __restrict__ rolls, int T)
{
    int i = blockIdx.x * blockDim.x + threadIdx.x;
    if (i < T + 96) g_rollpad[i] = rolls[(i < T) ? i : (T - 1)];
}

// Kernel 0b: no-op launch-index shims (keep ncu -s 5 landing on fwd_kernel)
__global__ void dummy_kernel() {}

// =====================================================================
// Kernel 1: serial Viterbi forward (values only). 256 threads, 8 warps
// (2/SMSP so co-resident warps hide each other's stalls).
// 4 lanes per state j = tid>>2; lane g = tid&3 covers i = 16g..16g+15.
// Combine via 2x shfl.bfly butterfly (full-warp shfl, NOT partial REDUX).
// =====================================================================
__global__ __launch_bounds__(256, 1)
void fwd_kernel(const int* __restrict__ rolls,
                const float* __restrict__ trans,
                const float* __restrict__ table, int T)
{
    __shared__ __align__(16) float smem_e[2][S];   // double-buffered e row
    __shared__ float smem_d[S];

    const int tid = threadIdx.x;
    const int j = tid >> 2;                        // state 0..63
    const int g = tid & 3;                         // candidate quarter

    float TR[16];
#pragma unroll
    for (int k = 0; k < 16; k++) TR[k] = trans[j * 65 + g * 16 + k];

    // ---- init: delta_0 = trans[:,64] + ll_0 ; e_1 = ll_1 + delta_0 ----
    {
        int r0 = rolls[0];
        int r1 = rolls[(T > 1) ? 1 : 0];
        float ll0 = table[r0 * S + j];
        float d0 = trans[j * 65 + 64] + ll0;
        if (T == 1 && g == 0) smem_d[j] = d0;
        float e1 = table[r1 * S + j] + d0;
        if (g == 0) smem_e[1][j] = e1;
        if (g == 1) g_e_buf[j] = e1;
    }
    // static 6-deep ll ring: llR[k] = ll_{t+1+k}, t=1 at entry -> ll_2..ll_7
    float llR0 = table[g_rollpad[2] * S + j];
    float llR1 = table[g_rollpad[3] * S + j];
    float llR2 = table[g_rollpad[4] * S + j];
    float llR3 = table[g_rollpad[5] * S + j];
    float llR4 = table[g_rollpad[6] * S + j];
    float llR5 = table[g_rollpad[7] * S + j];

    const int* rp = g_rollpad + 8;                 // rollpad[t+7] at t=1
    float* epp = g_e_buf + (size_t)S + j;          // e-store row for t=1
    __syncthreads();

    float delta = 0.0f;

    // One step, STATIC parity RP/WP, static offset OFF, static ring reg.
    // 4x LDS.128 (4 distinct 16B addrs, broadcast), 16 FFMA-imm (bit-exact),
    // quad tree, 2x shfl.bfly combine over the 4-lane group.
#define VSTEP(RP, WP, OFF, LLREG)                                              \
    {                                                                          \
        int rn = rp[OFF];                                                      \
        float llN = table[rn * S + j];                                         \
        float mq[4];                                                           \
        {                                                                      \
            const float4* eb =                                                 \
                reinterpret_cast<const float4*>(smem_e[RP]) + (g << 2);        \
            _Pragma("unroll")                                                  \
            for (int q = 0; q < 4; q++) {                                      \
                float4 f = eb[q];                                              \
                float a = __fmaf_rn(f.x, 1.0f, TR[4*q]);                       \
                float b = __fmaf_rn(f.y, 1.0f, TR[4*q+1]);                     \
                float c = __fmaf_rn(f.z, 1.0f, TR[4*q+2]);                     \
                float d = __fmaf_rn(f.w, 1.0f, TR[4*q+3]);                     \
                mq[q] = fmaxf(fmax3(a, b, c), d);                              \
            }                                                                  \
        }                                                                      \
        float m = fmaxf(fmax3(mq[0], mq[1], mq[2]), mq[3]);                    \
        float x1 = __shfl_xor_sync(0xffffffffu, m, 1);                         \
        float m1 = fmaxf(m, x1);                                               \
        float x2 = __shfl_xor_sync(0xffffffffu, m1, 2);                        \
        delta = fmaxf(m1, x2);                                                 \
        float ep = LLREG + delta;        /* e_{t+1} = ll_{t+1} + delta_t */    \
        if (g == 0) smem_e[WP][j] = ep;                                        \
        if (g == 1) epp[(OFF) * S] = ep;                                       \
        LLREG = llN;                      /* refill for step t+6 */            \
        __syncthreads();                                                       \
    }

    int t = 1;
    // main loop: 6 steps/iter; t odd at entry: parities (1,0),(0,1) x3
    for (; t + 5 < T; t += 6) {
        VSTEP(1, 0, 0, llR0);
        VSTEP(0, 1, 1, llR1);
        VSTEP(1, 0, 2, llR2);
        VSTEP(0, 1, 3, llR3);
        VSTEP(1, 0, 4, llR4);
        VSTEP(0, 1, 5, llR5);
        rp += 6;
        epp += 6 * S;
    }
#undef VSTEP

    // tail (<=5 steps): runtime parity, direct ll loads (stalls irrelevant)
    for (; t < T; t++) {
        const int rpar = t & 1, wpar = (t + 1) & 1;
        float mq[4];
        {
            const float4* eb = reinterpret_cast<const float4*>(smem_e[rpar]) + (g << 2);
#pragma unroll
            for (int q = 0; q < 4; q++) {
                float4 f = eb[q];
                float a = __fmaf_rn(f.x, 1.0f, TR[4*q]);
                float b = __fmaf_rn(f.y, 1.0f, TR[4*q+1]);
                float c = __fmaf_rn(f.z, 1.0f, TR[4*q+2]);
                float d = __fmaf_rn(f.w, 1.0f, TR[4*q+3]);
                mq[q] = fmaxf(fmax3(a, b, c), d);
            }
        }
        float m = fmaxf(fmax3(mq[0], mq[1], mq[2]), mq[3]);
        float x1 = __shfl_xor_sync(0xffffffffu, m, 1);
        float m1 = fmaxf(m, x1);
        float x2 = __shfl_xor_sync(0xffffffffu, m1, 2);
        delta = fmaxf(m1, x2);
        float ep = table[g_rollpad[t + 1] * S + j] + delta;
        if (g == 0) smem_e[wpar][j] = ep;
        if (g == 1) g_e_buf[(size_t)t * S + j] = ep;
        __syncthreads();
    }

    if (T > 1 && g == 0) smem_d[j] = delta;
    __syncthreads();
    if (tid == 0) {
        float best = smem_d[0]; int bi = 0;
        for (int q = 1; q < S; q++) {           // first-argmax (strict >)
            float vq = smem_d[q];
            if (vq > best) { best = vq; bi = q; }
        }
        g_final_state = bi;
        g_final_score = best;
    }
}

// =====================================================================
// Kernel 2: per-chunk backpointer recompute (bit-identical candidates,
// first-argmax via ascending strict >) + all-64-endstate backtrack walks.
// =====================================================================
__global__ __launch_bounds__(512, 1)
void bp_chunk_kernel(const float* __restrict__ trans, int T)
{
    __shared__ signed char bp_s[L * S];                 // 32 KB
    __shared__ __align__(16) float se[8][S];
    const int c = blockIdx.x;
    const int tid = threadIdx.x;
    const int tg = tid >> 6;
    const int j = tid & 63;
    int nr = (T - 1) - c * L; if (nr > L) nr = L; if (nr < 0) nr = 0;

    float TRv[64];
#pragma unroll
    for (int i = 0; i < 64; i++) TRv[i] = trans[j * 65 + i];

    for (int k = 0; k < L / 8; k++) {
        const int r = k * 8 + tg;
        const bool act = r < nr;
        if (act) se[tg][j] = g_e_buf[((size_t)(c * L + r)) * S + j];
        __syncthreads();
        if (act) {
            const float4* ep = reinterpret_cast<const float4*>(se[tg]);
            float4 e0 = ep[0];
            float m = TRv[0] + e0.x; int a = 0;
            float cc = TRv[1] + e0.y; if (cc > m) { m = cc; a = 1; }
            cc = TRv[2] + e0.z; if (cc > m) { m = cc; a = 2; }
            cc = TRv[3] + e0.w; if (cc > m) { m = cc; a = 3; }
#pragma unroll
            for (int q = 1; q < 16; q++) {
                float4 ev = ep[q];
                cc = TRv[4*q]   + ev.x; if (cc > m) { m = cc; a = 4*q;   }
                cc = TRv[4*q+1] + ev.y; if (cc > m) { m = cc; a = 4*q+1; }
                cc = TRv[4*q+2] + ev.z; if (cc > m) { m = cc; a = 4*q+2; }
                cc = TRv[4*q+3] + ev.w; if (cc > m) { m = cc; a = 4*q+3; }
            }
            bp_s[r * S + j] = (signed char)a;
        }
        __syncthreads();
    }

    if (tid < S) {
        int s = tid;
        const size_t wb = ((size_t)c * S + tid) * L;
        if (nr < L) g_walk[wb + nr] = (unsigned char)s;
        for (int r = nr - 1; r >= 0; r--) {
            s = bp_s[r * S + s];
            g_walk[wb + r] = (unsigned char)s;
        }
    }
}

// =====================================================================
// Kernel 3: serial chunk-map composition -> per-chunk boundary states
// =====================================================================
__global__ void compose_kernel(int T)
{
    __shared__ unsigned char mp[L * S];
    int nc = (T >= 2) ? ((T - 2) / L + 1) : 1;
    for (int q = threadIdx.x; q < nc * S; q += blockDim.x)
        mp[q] = g_walk[(size_t)q * L];
    __syncthreads();
    if (threadIdx.x == 0) {
        int s = g_final_state;
        g_boundary[nc] = s;
        for (int c = nc - 1; c >= 0; c--) {
            s = mp[c * S + s];
            g_boundary[c] = s;
        }
    }
}

// =====================================================================
// Kernel 4: parallel path fill, reverse-time order: out[T-1-t] = s_t
// =====================================================================
__global__ void fill_kernel(float* __restrict__ out, int T, int out_size)
{
    const int c = blockIdx.x;
    const int m = threadIdx.x;
    const int t = c * L + m;
    if (t < T) {
        const int sel = g_boundary[c + 1];
        unsigned char s = g_walk[((size_t)c * S + sel) * L + m];
        const int oi = T - 1 - t;
        if (oi >= 0 && oi < out_size) out[oi] = (float)s;
    }
    if (c == 0 && m == 0 && T < out_size) out[T] = g_final_score;
}

// =====================================================================
extern "C" void kernel_launch(void* const* d_in, const int* in_sizes, int n_in,
                              void* d_out, int out_size)
{
    const int* rolls = nullptr;
    const float* trans = nullptr;
    const float* table = nullptr;
    int T = 0;
    for (int i = 0; i < n_in; i++) {
        const int sz = in_sizes[i];
        if (sz == 64 * 65)       trans = (const float*)d_in[i];
        else if (sz == 128 * 64) table = (const float*)d_in[i];
        else { rolls = (const int*)d_in[i]; T = sz; }
    }
    if (!rolls || !trans || !table || T < 1) return;
    if (T > MAXT) T = MAXT;

    int nc = (T >= 2) ? ((T - 2) / L + 1) : 1;

    // 3 launches ahead of fwd so ncu's fixed "-s 5 -c 1" window lands on fwd.
    prep_kernel<<<(T + 96 + 255) / 256, 256>>>(rolls, T);
    dummy_kernel<<<1, 32>>>();
    dummy_kernel<<<1, 32>>>();

    fwd_kernel<<<1, 256>>>(rolls, trans, table, T);
    bp_chunk_kernel<<<nc, 512>>>(trans, T);
    compose_kernel<<<1, 256>>>(T);
    fill_kernel<<<nc, L>>>((float*)d_out, T, out_size);
}

// round 11
// speedup vs baseline: 2.3488x; 2.3488x over previous
#include <cuda_runtime.h>

#define S 64
#define MAXT 262144
#define L 512
#define NCMAX ((MAXT + L - 1) / L)

// ---- scratch (__device__ globals: no allocation allowed) ----
__device__ float g_e_buf[(size_t)(MAXT + 8) * S];              // e_t rows (+pad rows)
__device__ int g_rollpad[MAXT + 96];                           // rolls padded with last value
__device__ unsigned char g_walk[(size_t)NCMAX * S * L];        // per-chunk walks (16 MB)
__device__ int g_boundary[NCMAX + 2];
__device__ int g_final_state;
__device__ float g_final_score;

__device__ __forceinline__ float fmax3(float a, float b, float c) {
    return fmaxf(fmaxf(a, b), c);
}

// =====================================================================
// Kernel 0a: pad rolls so the serial loop needs no clamping
// =====================================================================
__global__ void prep_kernel(const int* __restrict__ rolls, int T)
{
    int i = blockIdx.x * blockDim.x + threadIdx.x;
    if (i < T + 96) g_rollpad[i] = rolls[(i < T) ? i : (T - 1)];
}

// Kernel 0b: no-op launch-index shims (keep ncu -s 5 landing on fwd_kernel)
__global__ void dummy_kernel() {}

// =====================================================================
// Kernel 1: serial Viterbi forward (values only). 128 threads, 4 warps
// (empirically optimal warp count). Thread pair per state j.
// 12-step unroll, dual 6-reg ll banks (distance-6 refill, no ring MOVs).
// =====================================================================
__global__ __launch_bounds__(128, 1)
void fwd_kernel(const int* __restrict__ rolls,
                const float* __restrict__ trans,
                const float* __restrict__ table, int T)
{
    // padded e layout: i<32 at [i], i>=32 at [36+i-32] -> bank-disjoint halves
    __shared__ __align__(16) float smem_e[2][68];
    __shared__ float smem_d[S];

    const int tid = threadIdx.x;
    const int w = tid >> 5, l = tid & 31;
    const int j = w * 16 + (l >> 1);
    const int half = l & 1;
    const int ibase = half << 5;
    const bool lead = (half == 0);
    const int pos = (j < 32) ? j : (36 + (j - 32));
    const int ebOff = half ? 36 : 0;

    float TR[32];
#pragma unroll
    for (int k = 0; k < 32; k++) TR[k] = trans[j * 65 + ibase + k];

    // ---- init: delta_0 = trans[:,64] + ll_0 ; e_1 = ll_1 + delta_0 ----
    {
        int r0 = rolls[0];
        int r1 = rolls[(T > 1) ? 1 : 0];
        float ll0 = table[r0 * S + j];
        float d0 = trans[j * 65 + 64] + ll0;
        if (T == 1 && lead) smem_d[j] = d0;
        float e1 = table[r1 * S + j] + d0;
        if (lead) smem_e[1][pos] = e1;
        else      g_e_buf[j] = e1;
    }
    // bank A: ll for steps t..t+5 (t=1 -> ll_2..ll_7); bank B refilled in-flight
    float llA0 = table[g_rollpad[2] * S + j];
    float llA1 = table[g_rollpad[3] * S + j];
    float llA2 = table[g_rollpad[4] * S + j];
    float llA3 = table[g_rollpad[5] * S + j];
    float llA4 = table[g_rollpad[6] * S + j];
    float llA5 = table[g_rollpad[7] * S + j];
    float llB0, llB1, llB2, llB3, llB4, llB5;

    const int* rp = g_rollpad + 8;                  // roll_{t+7} at t=1
    float* epp = g_e_buf + (size_t)S + j;           // e-store row for t=1
    __syncthreads();

    float delta = 0.0f;

    // One step: STATIC parity RP/WP, static store offset OFF (0..11),
    // consume LLSRC (ll_{t+OFF+1}), refill LLDST with ll_{t+OFF+7}.
    // Candidates via FFMA-imm (E*1.0+TR bit-exact, rt=1); FMNMX3-shaped
    // selection tree; shfl.bfly pair-combine.
#define VSTEP(RP, WP, OFF, LLSRC, LLDST)                                       \
    {                                                                          \
        int rn = rp[OFF];                                                      \
        LLDST = table[rn * S + j];                                             \
        float mq[8];                                                           \
        {                                                                      \
            const float4* eb =                                                 \
                reinterpret_cast<const float4*>(&smem_e[RP][ebOff]);           \
            _Pragma("unroll")                                                  \
            for (int q = 0; q < 8; q++) {                                      \
                float4 f = eb[q];                                              \
                float a = __fmaf_rn(f.x, 1.0f, TR[4*q]);                       \
                float b = __fmaf_rn(f.y, 1.0f, TR[4*q+1]);                     \
                float c = __fmaf_rn(f.z, 1.0f, TR[4*q+2]);                     \
                float d = __fmaf_rn(f.w, 1.0f, TR[4*q+3]);                     \
                mq[q] = fmaxf(fmax3(a, b, c), d);                              \
            }                                                                  \
        }                                                                      \
        float r0 = fmax3(mq[0], mq[1], mq[2]);                                 \
        float r1 = fmax3(mq[3], mq[4], mq[5]);                                 \
        float r2 = fmaxf(mq[6], mq[7]);                                        \
        float m  = fmax3(r0, r1, r2);                                          \
        float mo = __shfl_xor_sync(0xffffffffu, m, 1);                         \
        delta = fmaxf(m, mo);                                                  \
        float ep = LLSRC + delta;        /* e_{t+1} = ll_{t+1} + delta_t */    \
        if (lead) smem_e[WP][pos] = ep;                                        \
        else      epp[(OFF) * S] = ep;                                         \
        __syncthreads();                                                       \
    }

    int t = 1;
    // main loop: 12 steps/iter; t stays odd; parities (1,0),(0,1) repeating
    for (; t + 11 < T; t += 12) {
        VSTEP(1, 0, 0,  llA0, llB0);
        VSTEP(0, 1, 1,  llA1, llB1);
        VSTEP(1, 0, 2,  llA2, llB2);
        VSTEP(0, 1, 3,  llA3, llB3);
        VSTEP(1, 0, 4,  llA4, llB4);
        VSTEP(0, 1, 5,  llA5, llB5);
        VSTEP(1, 0, 6,  llB0, llA0);
        VSTEP(0, 1, 7,  llB1, llA1);
        VSTEP(1, 0, 8,  llB2, llA2);
        VSTEP(0, 1, 9,  llB3, llA3);
        VSTEP(1, 0, 10, llB4, llA4);
        VSTEP(0, 1, 11, llB5, llA5);
        rp += 12;
        epp += 12 * S;
    }
#undef VSTEP

    // tail (<=11 steps): runtime parity, direct ll loads (stalls irrelevant)
    for (; t < T; t++) {
        const int rpar = t & 1, wpar = (t + 1) & 1;
        float mq[8];
        {
            const float4* eb = reinterpret_cast<const float4*>(&smem_e[rpar][ebOff]);
#pragma unroll
            for (int q = 0; q < 8; q++) {
                float4 f = eb[q];
                float a = __fmaf_rn(f.x, 1.0f, TR[4*q]);
                float b = __fmaf_rn(f.y, 1.0f, TR[4*q+1]);
                float c = __fmaf_rn(f.z, 1.0f, TR[4*q+2]);
                float d = __fmaf_rn(f.w, 1.0f, TR[4*q+3]);
                mq[q] = fmaxf(fmax3(a, b, c), d);
            }
        }
        float r0 = fmax3(mq[0], mq[1], mq[2]);
        float r1 = fmax3(mq[3], mq[4], mq[5]);
        float r2 = fmaxf(mq[6], mq[7]);
        float m  = fmax3(r0, r1, r2);
        float mo = __shfl_xor_sync(0xffffffffu, m, 1);
        delta = fmaxf(m, mo);
        float ep = table[g_rollpad[t + 1] * S + j] + delta;
        if (lead) smem_e[wpar][pos] = ep;
        else      g_e_buf[(size_t)t * S + j] = ep;
        __syncthreads();
    }

    if (T > 1 && lead) smem_d[j] = delta;
    __syncthreads();
    if (tid == 0) {
        float best = smem_d[0]; int bi = 0;
        for (int q = 1; q < S; q++) {           // first-argmax (strict >)
            float vq = smem_d[q];
            if (vq > best) { best = vq; bi = q; }
        }
        g_final_state = bi;
        g_final_score = best;
    }
}

// =====================================================================
// Kernel 2: per-chunk backpointer recompute (bit-identical candidates,
// first-argmax via ascending strict >) + all-64-endstate backtrack walks.
// =====================================================================
__global__ __launch_bounds__(512, 1)
void bp_chunk_kernel(const float* __restrict__ trans, int T)
{
    __shared__ signed char bp_s[L * S];                 // 32 KB
    __shared__ __align__(16) float se[8][S];
    const int c = blockIdx.x;
    const int tid = threadIdx.x;
    const int tg = tid >> 6;
    const int j = tid & 63;
    int nr = (T - 1) - c * L; if (nr > L) nr = L; if (nr < 0) nr = 0;

    float TRv[64];
#pragma unroll
    for (int i = 0; i < 64; i++) TRv[i] = trans[j * 65 + i];

    for (int k = 0; k < L / 8; k++) {
        const int r = k * 8 + tg;
        const bool act = r < nr;
        if (act) se[tg][j] = g_e_buf[((size_t)(c * L + r)) * S + j];
        __syncthreads();
        if (act) {
            const float4* ep = reinterpret_cast<const float4*>(se[tg]);
            float4 e0 = ep[0];
            float m = TRv[0] + e0.x; int a = 0;
            float cc = TRv[1] + e0.y; if (cc > m) { m = cc; a = 1; }
            cc = TRv[2] + e0.z; if (cc > m) { m = cc; a = 2; }
            cc = TRv[3] + e0.w; if (cc > m) { m = cc; a = 3; }
#pragma unroll
            for (int q = 1; q < 16; q++) {
                float4 ev = ep[q];
                cc = TRv[4*q]   + ev.x; if (cc > m) { m = cc; a = 4*q;   }
                cc = TRv[4*q+1] + ev.y; if (cc > m) { m = cc; a = 4*q+1; }
                cc = TRv[4*q+2] + ev.z; if (cc > m) { m = cc; a = 4*q+2; }
                cc = TRv[4*q+3] + ev.w; if (cc > m) { m = cc; a = 4*q+3; }
            }
            bp_s[r * S + j] = (signed char)a;
        }
        __syncthreads();
    }

    if (tid < S) {
        int s = tid;
        const size_t wb = ((size_t)c * S + tid) * L;
        if (nr < L) g_walk[wb + nr] = (unsigned char)s;
        for (int r = nr - 1; r >= 0; r--) {
            s = bp_s[r * S + s];
            g_walk[wb + r] = (unsigned char)s;
        }
    }
}

// =====================================================================
// Kernel 3: serial chunk-map composition -> per-chunk boundary states
// =====================================================================
__global__ void compose_kernel(int T)
{
    __shared__ unsigned char mp[L * S];
    int nc = (T >= 2) ? ((T - 2) / L + 1) : 1;
    for (int q = threadIdx.x; q < nc * S; q += blockDim.x)
        mp[q] = g_walk[(size_t)q * L];
    __syncthreads();
    if (threadIdx.x == 0) {
        int s = g_final_state;
        g_boundary[nc] = s;
        for (int c = nc - 1; c >= 0; c--) {
            s = mp[c * S + s];
            g_boundary[c] = s;
        }
    }
}

// =====================================================================
// Kernel 4: parallel path fill, reverse-time order: out[T-1-t] = s_t
// =====================================================================
__global__ void fill_kernel(float* __restrict__ out, int T, int out_size)
{
    const int c = blockIdx.x;
    const int m = threadIdx.x;
    const int t = c * L + m;
    if (t < T) {
        const int sel = g_boundary[c + 1];
        unsigned char s = g_walk[((size_t)c * S + sel) * L + m];
        const int oi = T - 1 - t;
        if (oi >= 0 && oi < out_size) out[oi] = (float)s;
    }
    if (c == 0 && m == 0 && T < out_size) out[T] = g_final_score;
}

// =====================================================================
extern "C" void kernel_launch(void* const* d_in, const int* in_sizes, int n_in,
                              void* d_out, int out_size)
{
    const int* rolls = nullptr;
    const float* trans = nullptr;
    const float* table = nullptr;
    int T = 0;
    for (int i = 0; i < n_in; i++) {
        const int sz = in_sizes[i];
        if (sz == 64 * 65)       trans = (const float*)d_in[i];
        else if (sz == 128 * 64) table = (const float*)d_in[i];
        else { rolls = (const int*)d_in[i]; T = sz; }
    }
    if (!rolls || !trans || !table || T < 1) return;
    if (T > MAXT) T = MAXT;

    int nc = (T >= 2) ? ((T - 2) / L + 1) : 1;

    // 3 launches ahead of fwd so ncu's fixed "-s 5 -c 1" window lands on fwd.
    prep_kernel<<<(T + 96 + 255) / 256, 256>>>(rolls, T);
    dummy_kernel<<<1, 32>>>();
    dummy_kernel<<<1, 32>>>();

    fwd_kernel<<<1, 128>>>(rolls, trans, table, T);
    bp_chunk_kernel<<<nc, 512>>>(trans, T);
    compose_kernel<<<1, 256>>>(T);
    fill_kernel<<<nc, L>>>((float*)d_out, T, out_size);
}